// round 1
// baseline (speedup 1.0000x reference)
#include <cuda_runtime.h>
#include <math.h>

// Problem constants
#define TT    1024
#define DIMX  1024
#define HH    8
#define DK    192
#define DV    128
#define QLR   768
#define KVLR  512
#define DROPE 64

// ---------------- scratch (no allocations allowed) ----------------
__device__ float d_qa  [TT * QLR];          // x @ wq_a
__device__ float d_kva [TT * 576];          // x @ wkv_a  (512 + 64)
__device__ float d_eg  [TT * HH * DK];      // sigmoid(x @ wg_w + wg_b) == exp(log_sigmoid)
__device__ float d_beta[TT * HH];           // sigmoid(x @ wb)
__device__ float d_qn  [TT * QLR];          // rms(qa)
__device__ float d_kvn [TT * KVLR];         // rms(kva[:, :512])
__device__ float d_q   [TT * HH * DK];      // qn @ wq_b, then l2norm*DK^-0.5 in place
__device__ float d_kv  [TT * HH * 256];     // kvn @ wkv_b  (k_nope 128 | v 128 per head)
__device__ float d_kf  [TT * HH * DK];      // l2norm(concat(k_nope, k_pe))
__device__ float d_ov  [TT * HH * DV];      // recurrence output

// ---------------- SGEMM: C[M,N] = A[M,K] @ B[K,N] (+ bias, sigmoid) ----------------
// Requirements satisfied by all call sites: M%128==0, K%8==0, N%4==0.
#define BM 128
#define BN 128
#define BK 8
#define TM 8
#define TN 8

template <int EPI>  // 0 = none, 1 = sigmoid(v + bias[col])
__global__ __launch_bounds__(256, 2)
void sgemm_kernel(int M, int N, int K,
                  const float* __restrict__ A,
                  const float* __restrict__ B,
                  const float* __restrict__ bias,
                  float* __restrict__ C) {
    __shared__ float As[BK][BM];
    __shared__ float Bs[BK][BN];

    const int tid  = threadIdx.x;           // 256 threads
    const int crow = blockIdx.y * BM;
    const int ccol = blockIdx.x * BN;

    const int aRow = tid >> 1;               // 0..127
    const int aCol = (tid & 1) * 4;          // 0 or 4
    const int bRow = tid >> 5;               // 0..7
    const int bCol = (tid & 31) * 4;         // 0..124

    const int tr = (tid >> 4) * TM;          // 0..120
    const int tc = (tid & 15) * TN;          // 0..120

    float acc[TM][TN] = {};
    float ar[TM], br[TN];

    for (int k0 = 0; k0 < K; k0 += BK) {
        // A tile (always in range)
        float4 a4 = *reinterpret_cast<const float4*>(&A[(crow + aRow) * K + k0 + aCol]);
        As[aCol + 0][aRow] = a4.x;
        As[aCol + 1][aRow] = a4.y;
        As[aCol + 2][aRow] = a4.z;
        As[aCol + 3][aRow] = a4.w;
        // B tile (guard N; N%4==0 so a float4 is either fully in or fully out)
        const int gcol = ccol + bCol;
        float4 b4 = make_float4(0.f, 0.f, 0.f, 0.f);
        if (gcol < N)
            b4 = *reinterpret_cast<const float4*>(&B[(k0 + bRow) * N + gcol]);
        *reinterpret_cast<float4*>(&Bs[bRow][bCol]) = b4;
        __syncthreads();

        #pragma unroll
        for (int kk = 0; kk < BK; ++kk) {
            #pragma unroll
            for (int i = 0; i < TM; ++i) ar[i] = As[kk][tr + i];
            #pragma unroll
            for (int j = 0; j < TN; ++j) br[j] = Bs[kk][tc + j];
            #pragma unroll
            for (int i = 0; i < TM; ++i)
                #pragma unroll
                for (int j = 0; j < TN; ++j)
                    acc[i][j] += ar[i] * br[j];
        }
        __syncthreads();
    }

    #pragma unroll
    for (int i = 0; i < TM; ++i) {
        const int grow = crow + tr + i;
        #pragma unroll
        for (int j4 = 0; j4 < TN / 4; ++j4) {
            const int gcol = ccol + tc + j4 * 4;
            if (gcol < N) {
                float4 r;
                float v0 = acc[i][j4 * 4 + 0];
                float v1 = acc[i][j4 * 4 + 1];
                float v2 = acc[i][j4 * 4 + 2];
                float v3 = acc[i][j4 * 4 + 3];
                if (EPI == 1) {
                    v0 = 1.f / (1.f + expf(-(v0 + bias[gcol + 0])));
                    v1 = 1.f / (1.f + expf(-(v1 + bias[gcol + 1])));
                    v2 = 1.f / (1.f + expf(-(v2 + bias[gcol + 2])));
                    v3 = 1.f / (1.f + expf(-(v3 + bias[gcol + 3])));
                }
                r.x = v0; r.y = v1; r.z = v2; r.w = v3;
                *reinterpret_cast<float4*>(&C[(long)grow * N + gcol]) = r;
            }
        }
    }
}

// ---------------- beta = sigmoid(x @ wb), wb is [1024, 8] ----------------
__global__ void beta_kernel(const float* __restrict__ x,
                            const float* __restrict__ wb,
                            float* __restrict__ beta) {
    const int t = blockIdx.x;
    const int w = threadIdx.x >> 5;   // head 0..7 (8 warps)
    const int lane = threadIdx.x & 31;
    float acc = 0.f;
    const float* xr = x + t * DIMX;
    for (int i = lane; i < DIMX; i += 32)
        acc += xr[i] * wb[i * HH + w];
    #pragma unroll
    for (int off = 16; off; off >>= 1)
        acc += __shfl_xor_sync(0xffffffffu, acc, off);
    if (lane == 0)
        beta[t * HH + w] = 1.f / (1.f + expf(-acc));
}

// ---------------- row RMS norm: out = in * rsqrt(mean(in^2)+1e-5) * w ----------------
__global__ void rms_kernel(const float* __restrict__ in,
                           const float* __restrict__ w,
                           float* __restrict__ out,
                           int instride, int n, int outstride) {
    const int t = blockIdx.x;
    const float* row = in + (long)t * instride;
    float ss = 0.f;
    for (int i = threadIdx.x; i < n; i += 256) {
        float v = row[i];
        ss += v * v;
    }
    #pragma unroll
    for (int off = 16; off; off >>= 1)
        ss += __shfl_xor_sync(0xffffffffu, ss, off);
    __shared__ float red[8];
    __shared__ float scale_s;
    const int wid = threadIdx.x >> 5;
    if ((threadIdx.x & 31) == 0) red[wid] = ss;
    __syncthreads();
    if (threadIdx.x == 0) {
        float tot = 0.f;
        #pragma unroll
        for (int i = 0; i < 8; ++i) tot += red[i];
        scale_s = rsqrtf(tot / (float)n + 1e-5f);
    }
    __syncthreads();
    const float sc = scale_s;
    for (int i = threadIdx.x; i < n; i += 256)
        out[(long)t * outstride + i] = row[i] * sc * w[i];
}

// ---------------- prep: l2norm q (in place, *DK^-0.5), build + l2norm k ----------------
__global__ void prep_kernel(float* __restrict__ q,          // [T, H*192] in/out
                            const float* __restrict__ kv,   // [T, H*256]
                            const float* __restrict__ kva,  // [T, 576]
                            float* __restrict__ kf) {       // [T, H*192] out
    const int t = blockIdx.x >> 3;
    const int h = blockIdx.x & 7;
    const int i = threadIdx.x;  // 0..191

    const int qidx = t * (HH * DK) + h * DK + i;
    const float qv = q[qidx];
    const float kvv = (i < 128) ? kv[t * (HH * 256) + h * 256 + i]
                                : kva[t * 576 + KVLR + (i - 128)];

    float q2 = qv * qv, k2 = kvv * kvv;
    #pragma unroll
    for (int off = 16; off; off >>= 1) {
        q2 += __shfl_xor_sync(0xffffffffu, q2, off);
        k2 += __shfl_xor_sync(0xffffffffu, k2, off);
    }
    __shared__ float sq[6], sk[6];
    __shared__ float scl[2];
    const int wid = threadIdx.x >> 5;
    if ((threadIdx.x & 31) == 0) { sq[wid] = q2; sk[wid] = k2; }
    __syncthreads();
    if (threadIdx.x == 0) {
        float a = 0.f, b = 0.f;
        #pragma unroll
        for (int j = 0; j < 6; ++j) { a += sq[j]; b += sk[j]; }
        scl[0] = rsqrtf(a + 1e-6f) * 0.07216878364870322f;  // * DK^-0.5
        scl[1] = rsqrtf(b + 1e-6f);
    }
    __syncthreads();
    q[qidx] = qv * scl[0];
    kf[qidx] = kvv * scl[1];
}

// ---------------- KDA recurrence: one warp per (h, v) column ----------------
// S[:,v] (192 floats) lives in registers: 6 per lane (lane owns k = lane*6 .. lane*6+5)
__global__ __launch_bounds__(256)
void kda_rec(const float* __restrict__ qf,   // [T, H*192]
             const float* __restrict__ kf,   // [T, H*192]
             const float* __restrict__ eg,   // [T, H*192]
             const float* __restrict__ kv,   // [T, H*256], v at +128
             const float* __restrict__ beta, // [T, H]
             float* __restrict__ o) {        // [T, H*128]
    const int warp = (blockIdx.x * blockDim.x + threadIdx.x) >> 5;  // 0..1023
    const int lane = threadIdx.x & 31;
    const int h = warp >> 7;       // 0..7
    const int v = warp & 127;      // 0..127

    float s0 = 0.f, s1 = 0.f, s2 = 0.f, s3 = 0.f, s4 = 0.f, s5 = 0.f;
    const int kbase = h * DK + lane * 6;

    for (int t = 0; t < TT; ++t) {
        const int rb = t * (HH * DK) + kbase;
        const float2 e0 = *reinterpret_cast<const float2*>(eg + rb);
        const float2 e1 = *reinterpret_cast<const float2*>(eg + rb + 2);
        const float2 e2 = *reinterpret_cast<const float2*>(eg + rb + 4);
        const float2 k0 = *reinterpret_cast<const float2*>(kf + rb);
        const float2 k1 = *reinterpret_cast<const float2*>(kf + rb + 2);
        const float2 k2 = *reinterpret_cast<const float2*>(kf + rb + 4);
        const float2 q0 = *reinterpret_cast<const float2*>(qf + rb);
        const float2 q1 = *reinterpret_cast<const float2*>(qf + rb + 2);
        const float2 q2 = *reinterpret_cast<const float2*>(qf + rb + 4);
        const float vt = kv[t * (HH * 256) + h * 256 + 128 + v];
        const float bt = beta[t * HH + h];

        // S *= exp(g)
        s0 *= e0.x; s1 *= e0.y; s2 *= e1.x; s3 *= e1.y; s4 *= e2.x; s5 *= e2.y;

        // dot = k . S   (tree within lane, then butterfly across warp)
        float dot = (s0 * k0.x + s1 * k0.y) + (s2 * k1.x + s3 * k1.y) + (s4 * k2.x + s5 * k2.y);
        #pragma unroll
        for (int off = 16; off; off >>= 1)
            dot += __shfl_xor_sync(0xffffffffu, dot, off);

        const float u = bt * (vt - dot);

        // S += k * u ;  oacc = q . S
        s0 += k0.x * u; s1 += k0.y * u; s2 += k1.x * u;
        s3 += k1.y * u; s4 += k2.x * u; s5 += k2.y * u;
        float oacc = (s0 * q0.x + s1 * q0.y) + (s2 * q1.x + s3 * q1.y) + (s4 * q2.x + s5 * q2.y);
        #pragma unroll
        for (int off = 16; off; off >>= 1)
            oacc += __shfl_xor_sync(0xffffffffu, oacc, off);

        if (lane == 0) {
            float ov = oacc;
            if (ov != ov) ov = 0.f;                      // nan_to_num
            ov = fminf(fmaxf(ov, -10000.f), 10000.f);    // inf clamp
            o[t * (HH * DV) + h * DV + v] = ov;
        }
    }
}

// ---------------- launch ----------------
static inline dim3 gemm_grid(int M, int N) { return dim3((N + BN - 1) / BN, M / BM); }

extern "C" void kernel_launch(void* const* d_in, const int* in_sizes, int n_in,
                              void* d_out, int out_size) {
    (void)in_sizes; (void)n_in; (void)out_size;
    const float* x         = (const float*)d_in[0];
    // d_in[1] = cos, d_in[2] = sin : unused by the reference
    const float* wq_a      = (const float*)d_in[3];
    const float* q_norm_w  = (const float*)d_in[4];
    const float* wq_b      = (const float*)d_in[5];
    const float* wkv_a     = (const float*)d_in[6];
    const float* kv_norm_w = (const float*)d_in[7];
    const float* wkv_b     = (const float*)d_in[8];
    const float* wg_w      = (const float*)d_in[9];
    const float* wg_b      = (const float*)d_in[10];
    const float* wb        = (const float*)d_in[11];
    const float* wo        = (const float*)d_in[12];
    float* out = (float*)d_out;

    float *qa, *kva, *eg, *beta, *qn, *kvn, *q, *kv, *kf, *ov;
    cudaGetSymbolAddress((void**)&qa,   d_qa);
    cudaGetSymbolAddress((void**)&kva,  d_kva);
    cudaGetSymbolAddress((void**)&eg,   d_eg);
    cudaGetSymbolAddress((void**)&beta, d_beta);
    cudaGetSymbolAddress((void**)&qn,   d_qn);
    cudaGetSymbolAddress((void**)&kvn,  d_kvn);
    cudaGetSymbolAddress((void**)&q,    d_q);
    cudaGetSymbolAddress((void**)&kv,   d_kv);
    cudaGetSymbolAddress((void**)&kf,   d_kf);
    cudaGetSymbolAddress((void**)&ov,   d_ov);

    // Stage 1: projections from x
    sgemm_kernel<0><<<gemm_grid(TT, QLR),  256>>>(TT, QLR,  DIMX, x, wq_a,  nullptr, qa);
    sgemm_kernel<0><<<gemm_grid(TT, 576),  256>>>(TT, 576,  DIMX, x, wkv_a, nullptr, kva);
    sgemm_kernel<1><<<gemm_grid(TT, 1536), 256>>>(TT, 1536, DIMX, x, wg_w,  wg_b,    eg);
    beta_kernel<<<TT, 256>>>(x, wb, beta);

    // Stage 2: RMS norms
    rms_kernel<<<TT, 256>>>(qa,  q_norm_w,  qn,  QLR, QLR,  QLR);
    rms_kernel<<<TT, 256>>>(kva, kv_norm_w, kvn, 576, KVLR, KVLR);

    // Stage 3: up-projections
    sgemm_kernel<0><<<gemm_grid(TT, 1536), 256>>>(TT, 1536, QLR,  qn,  wq_b,  nullptr, q);
    sgemm_kernel<0><<<gemm_grid(TT, 2048), 256>>>(TT, 2048, KVLR, kvn, wkv_b, nullptr, kv);

    // Stage 4: l2norm q/k, assemble k
    prep_kernel<<<TT * HH, 192>>>(q, kv, kva, kf);

    // Stage 5: sequential KDA recurrence (warp per (h,v) column)
    kda_rec<<<128, 256>>>(q, kf, eg, kv, beta, ov);

    // Stage 6: output projection
    sgemm_kernel<0><<<gemm_grid(TT, DIMX), 256>>>(TT, DIMX, DIMX, ov, wo, nullptr, out);
}

// round 3
// speedup vs baseline: 1.3769x; 1.3769x over previous
#include <cuda_runtime.h>
#include <math.h>

// Problem constants
#define TT    1024
#define DIMX  1024
#define HH    8
#define DK    192
#define DV    128
#define QLR   768
#define KVLR  512
#define DROPE 64

// Stage-1 concatenated layout (columns of big buffer):
//   [0,768)      qa  = x @ wq_a
//   [768,1344)   kva = x @ wkv_a        (cols 1280..1343 = k_pe)
//   [1344,2880)  eg  = sigmoid(x @ wg_w + wg_b)
//   [2880,2888)  beta= sigmoid(x @ wb)
//   [2888,2944)  pad
#define NBIG 2944

// ---------------- scratch (no allocations allowed) ----------------
__device__ float d_bc  [DIMX * NBIG];       // concatenated stage-1 weights
__device__ float d_big [TT * NBIG];         // stage-1 outputs
__device__ float d_qn  [TT * QLR];          // rms(qa)
__device__ float d_kvn [TT * KVLR];         // rms(kva[:, :512])
__device__ float d_q   [TT * HH * DK];      // qn @ wq_b, then l2norm*DK^-0.5 in place
__device__ float d_kv  [TT * HH * 256];     // kvn @ wkv_b (k_nope 128 | v 128 per head)
__device__ float d_kf  [TT * HH * DK];      // l2norm(concat(k_nope, k_pe))
__device__ float d_ov  [TT * HH * DV];      // recurrence output

// ================= TF32 tensor-core GEMM =================
#define BM 128
#define BN 128
#define BK 16

__device__ __forceinline__ unsigned f2tf(float f) {
    unsigned u;
    asm("cvt.rna.tf32.f32 %0, %1;" : "=r"(u) : "f"(f));
    return u;
}

__device__ __forceinline__ void mma_tf32(float* c, const unsigned* a, const unsigned* b) {
    asm volatile(
        "mma.sync.aligned.m16n8k8.row.col.f32.tf32.tf32.f32 "
        "{%0,%1,%2,%3}, {%4,%5,%6,%7}, {%8,%9}, {%0,%1,%2,%3};\n"
        : "+f"(c[0]), "+f"(c[1]), "+f"(c[2]), "+f"(c[3])
        : "r"(a[0]), "r"(a[1]), "r"(a[2]), "r"(a[3]), "r"(b[0]), "r"(b[1]));
}

// EPI: 0 = none, 1 = stage-1 column-range epilogue (sigmoid for g/beta ranges)
__device__ __forceinline__ float epi1(float v, int gc, const float* __restrict__ bias) {
    if (gc >= 1344 && gc < 2888) {
        float b = (gc < 2880) ? bias[gc - 1344] : 0.f;
        v = 1.f / (1.f + expf(-(v + b)));
    }
    return v;
}

template <int EPI>
__device__ __forceinline__ void tgemm_core(int N, int K,
                                           const float* __restrict__ A, int lda,
                                           const float* __restrict__ B, int ldb,
                                           const float* __restrict__ bias,
                                           float* __restrict__ C, int ldc) {
    __shared__ unsigned As[BK][BM];
    __shared__ unsigned Bs[BK][BN];

    const int tid  = threadIdx.x;             // 256 threads = 8 warps
    const int crow = blockIdx.y * BM;
    const int ccol = blockIdx.x * BN;

    const int wid  = tid >> 5;
    const int lane = tid & 31;
    const int lq   = lane >> 2;   // 0..7
    const int lr   = lane & 3;    // 0..3
    const int rm   = (wid & 1) * 64;   // warp row base (2 warps in M)
    const int cn   = (wid >> 1) * 32;  // warp col base (4 warps in N)

    const int am = tid >> 1, ak = (tid & 1) * 8;   // A tile load map
    const int bk = tid >> 4, bc = (tid & 15) * 8;  // B tile load map

    float acc[4][4][4] = {};

    for (int k0 = 0; k0 < K; k0 += BK) {
        // A: [BM][BK] transposed into As[k][m], tf32-converted
        const float* ap = &A[(long)(crow + am) * lda + k0 + ak];
        float4 a0 = *reinterpret_cast<const float4*>(ap);
        float4 a1 = *reinterpret_cast<const float4*>(ap + 4);
        As[ak + 0][am] = f2tf(a0.x); As[ak + 1][am] = f2tf(a0.y);
        As[ak + 2][am] = f2tf(a0.z); As[ak + 3][am] = f2tf(a0.w);
        As[ak + 4][am] = f2tf(a1.x); As[ak + 5][am] = f2tf(a1.y);
        As[ak + 6][am] = f2tf(a1.z); As[ak + 7][am] = f2tf(a1.w);
        // B: direct [BK][BN]
        const float* bp = &B[(long)(k0 + bk) * ldb + ccol + bc];
        float4 b0 = *reinterpret_cast<const float4*>(bp);
        float4 b1 = *reinterpret_cast<const float4*>(bp + 4);
        uint4 u0 = make_uint4(f2tf(b0.x), f2tf(b0.y), f2tf(b0.z), f2tf(b0.w));
        uint4 u1 = make_uint4(f2tf(b1.x), f2tf(b1.y), f2tf(b1.z), f2tf(b1.w));
        *reinterpret_cast<uint4*>(&Bs[bk][bc])     = u0;
        *reinterpret_cast<uint4*>(&Bs[bk][bc + 4]) = u1;
        __syncthreads();

        #pragma unroll
        for (int k8 = 0; k8 < BK; k8 += 8) {
            unsigned af[4][4], bf[4][2];
            #pragma unroll
            for (int mt = 0; mt < 4; ++mt) {
                const int r = rm + mt * 16 + lq;
                af[mt][0] = As[k8 + lr][r];
                af[mt][1] = As[k8 + lr][r + 8];
                af[mt][2] = As[k8 + lr + 4][r];
                af[mt][3] = As[k8 + lr + 4][r + 8];
            }
            #pragma unroll
            for (int nt = 0; nt < 4; ++nt) {
                const int c = cn + nt * 8 + lq;
                bf[nt][0] = Bs[k8 + lr][c];
                bf[nt][1] = Bs[k8 + lr + 4][c];
            }
            #pragma unroll
            for (int mt = 0; mt < 4; ++mt)
                #pragma unroll
                for (int nt = 0; nt < 4; ++nt)
                    mma_tf32(acc[mt][nt], af[mt], bf[nt]);
        }
        __syncthreads();
    }

    #pragma unroll
    for (int mt = 0; mt < 4; ++mt) {
        const int row = crow + rm + mt * 16 + lq;
        #pragma unroll
        for (int nt = 0; nt < 4; ++nt) {
            const int col = ccol + cn + nt * 8 + lr * 2;
            float v0 = acc[mt][nt][0], v1 = acc[mt][nt][1];
            float v2 = acc[mt][nt][2], v3 = acc[mt][nt][3];
            if (EPI == 1) {
                v0 = epi1(v0, col, bias);     v1 = epi1(v1, col + 1, bias);
                v2 = epi1(v2, col, bias);     v3 = epi1(v3, col + 1, bias);
            }
            *reinterpret_cast<float2*>(&C[(long)row * ldc + col])       = make_float2(v0, v1);
            *reinterpret_cast<float2*>(&C[(long)(row + 8) * ldc + col]) = make_float2(v2, v3);
        }
    }
}

template <int EPI>
__global__ __launch_bounds__(256)
void tgemm_kernel(int N, int K, const float* __restrict__ A, int lda,
                  const float* __restrict__ B, int ldb,
                  const float* __restrict__ bias, float* __restrict__ C, int ldc) {
    tgemm_core<EPI>(N, K, A, lda, B, ldb, bias, C, ldc);
}

// Two problems batched via blockIdx.z (different A / B / K / N)
__global__ __launch_bounds__(256)
void tgemm_dual_kernel(int N0, int K0, const float* __restrict__ A0,
                       const float* __restrict__ B0, float* __restrict__ C0,
                       int N1, int K1, const float* __restrict__ A1,
                       const float* __restrict__ B1, float* __restrict__ C1) {
    if (blockIdx.z == 0) {
        if ((int)blockIdx.x * BN >= N0) return;
        tgemm_core<0>(N0, K0, A0, K0, B0, N0, nullptr, C0, N0);
    } else {
        tgemm_core<0>(N1, K1, A1, K1, B1, N1, nullptr, C1, N1);
    }
}

// ---------------- stage-1 weight concat: [1024][2944] ----------------
__global__ void concat_w(const float* __restrict__ wq_a,
                         const float* __restrict__ wkv_a,
                         const float* __restrict__ wg_w,
                         const float* __restrict__ wb,
                         float* __restrict__ Bc) {
    const int c = blockIdx.x * 128 + threadIdx.x;
    const int r = blockIdx.y;
    float v;
    if      (c < 768)  v = wq_a [r * 768  + c];
    else if (c < 1344) v = wkv_a[r * 576  + (c - 768)];
    else if (c < 2880) v = wg_w [r * 1536 + (c - 1344)];
    else if (c < 2888) v = wb   [r * 8    + (c - 2880)];
    else               v = 0.f;
    Bc[(long)r * NBIG + c] = v;
}

// ---------------- row RMS norm ----------------
__global__ void rms_kernel(const float* __restrict__ in, int inoff, int instride,
                           const float* __restrict__ w,
                           float* __restrict__ out, int n) {
    const int t = blockIdx.x;
    const float* row = in + (long)t * instride + inoff;
    float ss = 0.f;
    for (int i = threadIdx.x; i < n; i += 256) {
        float v = row[i];
        ss += v * v;
    }
    #pragma unroll
    for (int off = 16; off; off >>= 1)
        ss += __shfl_xor_sync(0xffffffffu, ss, off);
    __shared__ float red[8];
    __shared__ float scale_s;
    const int wid = threadIdx.x >> 5;
    if ((threadIdx.x & 31) == 0) red[wid] = ss;
    __syncthreads();
    if (threadIdx.x == 0) {
        float tot = 0.f;
        #pragma unroll
        for (int i = 0; i < 8; ++i) tot += red[i];
        scale_s = rsqrtf(tot / (float)n + 1e-5f);
    }
    __syncthreads();
    const float sc = scale_s;
    for (int i = threadIdx.x; i < n; i += 256)
        out[(long)t * n + i] = row[i] * sc * w[i];
}

// ---------------- prep: l2norm q (in place, *DK^-0.5), build + l2norm k ----------------
__global__ void prep_kernel(float* __restrict__ q,          // [T, H*192] in/out
                            const float* __restrict__ kv,   // [T, H*256]
                            const float* __restrict__ big,  // k_pe at col 1280
                            float* __restrict__ kf) {       // [T, H*192] out
    const int t = blockIdx.x >> 3;
    const int h = blockIdx.x & 7;
    const int i = threadIdx.x;  // 0..191

    const int qidx = t * (HH * DK) + h * DK + i;
    const float qv = q[qidx];
    const float kvv = (i < 128) ? kv[t * (HH * 256) + h * 256 + i]
                                : big[(long)t * NBIG + 1280 + (i - 128)];

    float q2 = qv * qv, k2 = kvv * kvv;
    #pragma unroll
    for (int off = 16; off; off >>= 1) {
        q2 += __shfl_xor_sync(0xffffffffu, q2, off);
        k2 += __shfl_xor_sync(0xffffffffu, k2, off);
    }
    __shared__ float sq[6], sk[6];
    __shared__ float scl[2];
    const int wid = threadIdx.x >> 5;
    if ((threadIdx.x & 31) == 0) { sq[wid] = q2; sk[wid] = k2; }
    __syncthreads();
    if (threadIdx.x == 0) {
        float a = 0.f, b = 0.f;
        #pragma unroll
        for (int j = 0; j < 6; ++j) { a += sq[j]; b += sk[j]; }
        scl[0] = rsqrtf(a + 1e-6f) * 0.07216878364870322f;  // * DK^-0.5
        scl[1] = rsqrtf(b + 1e-6f);
    }
    __syncthreads();
    q[qidx] = qv * scl[0];
    kf[qidx] = kvv * scl[1];
}

// ---------------- KDA recurrence: one warp per (h, v) column ----------------
__global__ __launch_bounds__(256)
void kda_rec(const float* __restrict__ qf,   // [T, H*192]
             const float* __restrict__ kf,   // [T, H*192]
             const float* __restrict__ big,  // eg at col 1344, beta at col 2880
             const float* __restrict__ kv,   // [T, H*256], v at +128
             float* __restrict__ o) {        // [T, H*128]
    const int warp = (blockIdx.x * blockDim.x + threadIdx.x) >> 5;  // 0..1023
    const int lane = threadIdx.x & 31;
    const int h = warp >> 7;       // 0..7
    const int v = warp & 127;      // 0..127

    float s0 = 0.f, s1 = 0.f, s2 = 0.f, s3 = 0.f, s4 = 0.f, s5 = 0.f;
    const int kbase = h * DK + lane * 6;

    for (int t = 0; t < TT; ++t) {
        const int rb = t * (HH * DK) + kbase;
        const long eb = (long)t * NBIG + 1344 + kbase;
        const float2 e0 = *reinterpret_cast<const float2*>(big + eb);
        const float2 e1 = *reinterpret_cast<const float2*>(big + eb + 2);
        const float2 e2 = *reinterpret_cast<const float2*>(big + eb + 4);
        const float2 k0 = *reinterpret_cast<const float2*>(kf + rb);
        const float2 k1 = *reinterpret_cast<const float2*>(kf + rb + 2);
        const float2 k2 = *reinterpret_cast<const float2*>(kf + rb + 4);
        const float2 q0 = *reinterpret_cast<const float2*>(qf + rb);
        const float2 q1 = *reinterpret_cast<const float2*>(qf + rb + 2);
        const float2 q2 = *reinterpret_cast<const float2*>(qf + rb + 4);
        const float vt = kv[t * (HH * 256) + h * 256 + 128 + v];
        const float bt = big[(long)t * NBIG + 2880 + h];

        // S *= exp(g)
        s0 *= e0.x; s1 *= e0.y; s2 *= e1.x; s3 *= e1.y; s4 *= e2.x; s5 *= e2.y;

        // dot = k . S
        float dot = (s0 * k0.x + s1 * k0.y) + (s2 * k1.x + s3 * k1.y) + (s4 * k2.x + s5 * k2.y);
        #pragma unroll
        for (int off = 16; off; off >>= 1)
            dot += __shfl_xor_sync(0xffffffffu, dot, off);

        const float u = bt * (vt - dot);

        // S += k * u ;  oacc = q . S
        s0 += k0.x * u; s1 += k0.y * u; s2 += k1.x * u;
        s3 += k1.y * u; s4 += k2.x * u; s5 += k2.y * u;
        float oacc = (s0 * q0.x + s1 * q0.y) + (s2 * q1.x + s3 * q1.y) + (s4 * q2.x + s5 * q2.y);
        #pragma unroll
        for (int off = 16; off; off >>= 1)
            oacc += __shfl_xor_sync(0xffffffffu, oacc, off);

        if (lane == 0) {
            float ov = oacc;
            if (ov != ov) ov = 0.f;                      // nan_to_num
            ov = fminf(fmaxf(ov, -10000.f), 10000.f);    // inf clamp
            o[t * (HH * DV) + h * DV + v] = ov;
        }
    }
}

// ---------------- launch ----------------
extern "C" void kernel_launch(void* const* d_in, const int* in_sizes, int n_in,
                              void* d_out, int out_size) {
    (void)in_sizes; (void)n_in; (void)out_size;
    const float* x         = (const float*)d_in[0];
    // d_in[1] = cos, d_in[2] = sin : unused by the reference
    const float* wq_a      = (const float*)d_in[3];
    const float* q_norm_w  = (const float*)d_in[4];
    const float* wq_b      = (const float*)d_in[5];
    const float* wkv_a     = (const float*)d_in[6];
    const float* kv_norm_w = (const float*)d_in[7];
    const float* wkv_b     = (const float*)d_in[8];
    const float* wg_w      = (const float*)d_in[9];
    const float* wg_b      = (const float*)d_in[10];
    const float* wb        = (const float*)d_in[11];
    const float* wo        = (const float*)d_in[12];
    float* out = (float*)d_out;

    float *bc, *big, *qn, *kvn, *q, *kv, *kf, *ov;
    cudaGetSymbolAddress((void**)&bc,  d_bc);
    cudaGetSymbolAddress((void**)&big, d_big);
    cudaGetSymbolAddress((void**)&qn,  d_qn);
    cudaGetSymbolAddress((void**)&kvn, d_kvn);
    cudaGetSymbolAddress((void**)&q,   d_q);
    cudaGetSymbolAddress((void**)&kv,  d_kv);
    cudaGetSymbolAddress((void**)&kf,  d_kf);
    cudaGetSymbolAddress((void**)&ov,  d_ov);

    // Stage 0: concat stage-1 weights
    concat_w<<<dim3(NBIG / 128, DIMX), 128>>>(wq_a, wkv_a, wg_w, wb, bc);

    // Stage 1: one wide tensor-core GEMM: big = x @ [wq_a | wkv_a | wg_w | wb] (+epilogues)
    tgemm_kernel<1><<<dim3(NBIG / BN, TT / BM), 256>>>(NBIG, DIMX, x, DIMX, bc, NBIG, wg_b, big, NBIG);

    // Stage 2: RMS norms (read from big)
    rms_kernel<<<TT, 256>>>(big, 0,   NBIG, q_norm_w,  qn,  QLR);
    rms_kernel<<<TT, 256>>>(big, 768, NBIG, kv_norm_w, kvn, KVLR);

    // Stage 3: batched up-projections (z routes problem)
    tgemm_dual_kernel<<<dim3(2048 / BN, TT / BM, 2), 256>>>(
        1536, QLR,  qn,  wq_b,  q,
        2048, KVLR, kvn, wkv_b, kv);

    // Stage 4: l2norm q/k, assemble k
    prep_kernel<<<TT * HH, 192>>>(q, kv, big, kf);

    // Stage 5: sequential KDA recurrence
    kda_rec<<<128, 256>>>(q, kf, big, kv, ov);

    // Stage 6: output projection
    tgemm_kernel<0><<<dim3(DIMX / BN, TT / BM), 256>>>(DIMX, DIMX, ov, DIMX, wo, DIMX, nullptr, out, DIMX);
}

// round 4
// speedup vs baseline: 3.5410x; 2.5717x over previous
#include <cuda_runtime.h>
#include <math.h>

// Problem constants
#define TT    1024
#define DIMX  1024
#define HH    8
#define DK    192
#define DV    128
#define QLR   768
#define KVLR  512
#define DROPE 64

// Stage-1 concatenated layout (columns of big buffer):
//   [0,768)      qa  = x @ wq_a
//   [768,1344)   kva = x @ wkv_a        (cols 1280..1343 = k_pe)
//   [1344,2880)  eg  = sigmoid(x @ wg_w + wg_b)
//   [2880,2888)  beta= sigmoid(x @ wb)
//   [2888,2944)  pad
#define NBIG 2944

// ---------------- scratch (no allocations allowed) ----------------
__device__ float d_bc  [DIMX * NBIG];
__device__ float d_big [TT * NBIG];
__device__ float d_qn  [TT * QLR];
__device__ float d_kvn [TT * KVLR];
__device__ float d_q   [TT * HH * DK];
__device__ float d_kv  [TT * HH * 256];
__device__ float d_kf  [TT * HH * DK];
__device__ float d_ov  [TT * HH * DV];

// ================= TF32 tensor-core GEMM =================
#define BM 64
#define BN 128
#define BK 16

__device__ __forceinline__ unsigned f2tf(float f) {
    unsigned u;
    asm("cvt.rna.tf32.f32 %0, %1;" : "=r"(u) : "f"(f));
    return u;
}

__device__ __forceinline__ void mma_tf32(float* c, const unsigned* a, const unsigned* b) {
    asm volatile(
        "mma.sync.aligned.m16n8k8.row.col.f32.tf32.tf32.f32 "
        "{%0,%1,%2,%3}, {%4,%5,%6,%7}, {%8,%9}, {%0,%1,%2,%3};\n"
        : "+f"(c[0]), "+f"(c[1]), "+f"(c[2]), "+f"(c[3])
        : "r"(a[0]), "r"(a[1]), "r"(a[2]), "r"(a[3]), "r"(b[0]), "r"(b[1]));
}

// EPI: 0 = none, 1 = stage-1 column-range epilogue (sigmoid for g/beta ranges)
__device__ __forceinline__ float epi1(float v, int gc, const float* __restrict__ bias) {
    if (gc >= 1344 && gc < 2888) {
        float b = (gc < 2880) ? bias[gc - 1344] : 0.f;
        v = 1.f / (1.f + expf(-(v + b)));
    }
    return v;
}

// Single-buffer smem, register-prefetch pipelined, XOR-swizzled (conflict-free
// fragment loads and A-transpose stores). PREC: 1 = tf32, 3 = 3xTF32 (hi/lo).
template <int EPI, int PREC>
__device__ __forceinline__ void tgemm_core(int N, int K,
                                           const float* __restrict__ A, int lda,
                                           const float* __restrict__ B, int ldb,
                                           const float* __restrict__ bias,
                                           float* __restrict__ C, int ldc,
                                           unsigned* sA, unsigned* sB) {
    constexpr int PL = (PREC == 3) ? 2 : 1;

    const int tid  = threadIdx.x;             // 256 threads = 8 warps
    const int crow = blockIdx.y * BM;
    const int ccol = blockIdx.x * BN;

    const int wid  = tid >> 5;
    const int lane = tid & 31;
    const int lq   = lane >> 2;        // 0..7
    const int lr   = lane & 3;         // 0..3
    const int rm   = (wid & 1) * 32;   // warp row base (2 warps in M)
    const int cn   = (wid >> 1) * 32;  // warp col base (4 warps in N)

    // loaders: A one float4/thread, B two float4/thread
    const int am  = tid >> 2;          // 0..63
    const int ak4 = (tid & 3) * 4;     // 0,4,8,12
    const int bk  = tid >> 4;          // 0..15
    const int bc8 = (tid & 15) * 8;    // 0..120

    float acc[2][4][4] = {};
    float4 aR, bR0, bR1;

    // prefetch first tile
    aR  = *reinterpret_cast<const float4*>(&A[(long)(crow + am) * lda + ak4]);
    bR0 = *reinterpret_cast<const float4*>(&B[(long)bk * ldb + ccol + bc8]);
    bR1 = *reinterpret_cast<const float4*>(&B[(long)bk * ldb + ccol + bc8 + 4]);

    for (int k0 = 0; k0 < K; k0 += BK) {
        // ---- store prefetched tile to smem (tf32 cvt, transposed A, swizzled) ----
        {
            const float av[4] = {aR.x, aR.y, aR.z, aR.w};
            #pragma unroll
            for (int i = 0; i < 4; ++i) {
                const int k  = ak4 + i;
                const int sw = (((k & 3) ^ ((k >> 2) & 3)) << 3);
                unsigned hi = f2tf(av[i]);
                sA[k * BM + (am ^ sw)] = hi;
                if (PREC == 3)
                    sA[BK * BM + k * BM + (am ^ sw)] = f2tf(av[i] - __uint_as_float(hi));
            }
            const int swb = (((bk & 3) ^ ((bk >> 2) & 3)) << 3);
            const float bv[8] = {bR0.x, bR0.y, bR0.z, bR0.w, bR1.x, bR1.y, bR1.z, bR1.w};
            #pragma unroll
            for (int h = 0; h < 8; h += 4) {
                const int cc = (bc8 + h) ^ swb;
                #pragma unroll
                for (int i = 0; i < 4; ++i) {
                    unsigned hi = f2tf(bv[h + i]);
                    sB[bk * BN + cc + i] = hi;
                    if (PREC == 3)
                        sB[BK * BN + bk * BN + cc + i] = f2tf(bv[h + i] - __uint_as_float(hi));
                }
            }
        }
        __syncthreads();

        // ---- prefetch next tile into registers ----
        if (k0 + BK < K) {
            aR  = *reinterpret_cast<const float4*>(&A[(long)(crow + am) * lda + k0 + BK + ak4]);
            bR0 = *reinterpret_cast<const float4*>(&B[(long)(k0 + BK + bk) * ldb + ccol + bc8]);
            bR1 = *reinterpret_cast<const float4*>(&B[(long)(k0 + BK + bk) * ldb + ccol + bc8 + 4]);
        }

        // ---- compute on current smem tile ----
        #pragma unroll
        for (int k8 = 0; k8 < BK; k8 += 8) {
            const int f0 = ((lr ^ (k8 >> 2)) & 3) << 3;  // swizzle for rows k8+lr
            const int f1 = f0 ^ 8;                       // rows k8+lr+4
            unsigned af[PL][2][4], bf[PL][4][2];
            #pragma unroll
            for (int pl = 0; pl < PL; ++pl) {
                const unsigned* a = sA + pl * (BK * BM);
                #pragma unroll
                for (int mt = 0; mt < 2; ++mt) {
                    const int r = rm + mt * 16 + lq;
                    af[pl][mt][0] = a[(k8 + lr) * BM + (r ^ f0)];
                    af[pl][mt][1] = a[(k8 + lr) * BM + ((r + 8) ^ f0)];
                    af[pl][mt][2] = a[(k8 + lr + 4) * BM + (r ^ f1)];
                    af[pl][mt][3] = a[(k8 + lr + 4) * BM + ((r + 8) ^ f1)];
                }
                const unsigned* b = sB + pl * (BK * BN);
                #pragma unroll
                for (int nt = 0; nt < 4; ++nt) {
                    const int c = cn + nt * 8 + lq;
                    bf[pl][nt][0] = b[(k8 + lr) * BN + (c ^ f0)];
                    bf[pl][nt][1] = b[(k8 + lr + 4) * BN + (c ^ f1)];
                }
            }
            #pragma unroll
            for (int mt = 0; mt < 2; ++mt)
                #pragma unroll
                for (int nt = 0; nt < 4; ++nt) {
                    mma_tf32(acc[mt][nt], af[0][mt], bf[0][nt]);
                    if (PREC == 3) {
                        mma_tf32(acc[mt][nt], af[0][mt], bf[1][nt]);
                        mma_tf32(acc[mt][nt], af[1][mt], bf[0][nt]);
                    }
                }
        }
        __syncthreads();
    }

    #pragma unroll
    for (int mt = 0; mt < 2; ++mt) {
        const int row = crow + rm + mt * 16 + lq;
        #pragma unroll
        for (int nt = 0; nt < 4; ++nt) {
            const int col = ccol + cn + nt * 8 + lr * 2;
            float v0 = acc[mt][nt][0], v1 = acc[mt][nt][1];
            float v2 = acc[mt][nt][2], v3 = acc[mt][nt][3];
            if (EPI == 1) {
                v0 = epi1(v0, col, bias);     v1 = epi1(v1, col + 1, bias);
                v2 = epi1(v2, col, bias);     v3 = epi1(v3, col + 1, bias);
            }
            *reinterpret_cast<float2*>(&C[(long)row * ldc + col])       = make_float2(v0, v1);
            *reinterpret_cast<float2*>(&C[(long)(row + 8) * ldc + col]) = make_float2(v2, v3);
        }
    }
}

template <int EPI, int PREC>
__global__ __launch_bounds__(256, 2)
void tgemm_kernel(int N, int K, const float* __restrict__ A, int lda,
                  const float* __restrict__ B, int ldb,
                  const float* __restrict__ bias, float* __restrict__ C, int ldc) {
    constexpr int PL = (PREC == 3) ? 2 : 1;
    __shared__ unsigned sA[PL * BK * BM];
    __shared__ unsigned sB[PL * BK * BN];
    tgemm_core<EPI, PREC>(N, K, A, lda, B, ldb, bias, C, ldc, sA, sB);
}

// Two problems batched via blockIdx.z (shared smem, exclusive branches)
__global__ __launch_bounds__(256, 2)
void tgemm_dual_kernel(int N0, int K0, const float* __restrict__ A0,
                       const float* __restrict__ B0, float* __restrict__ C0,
                       int N1, int K1, const float* __restrict__ A1,
                       const float* __restrict__ B1, float* __restrict__ C1) {
    __shared__ unsigned sA[BK * BM];
    __shared__ unsigned sB[BK * BN];
    if (blockIdx.z == 0) {
        if ((int)blockIdx.x * BN >= N0) return;
        tgemm_core<0, 1>(N0, K0, A0, K0, B0, N0, nullptr, C0, N0, sA, sB);
    } else {
        tgemm_core<0, 1>(N1, K1, A1, K1, B1, N1, nullptr, C1, N1, sA, sB);
    }
}

// ---------------- stage-1 weight concat: [1024][2944] ----------------
__global__ void concat_w(const float* __restrict__ wq_a,
                         const float* __restrict__ wkv_a,
                         const float* __restrict__ wg_w,
                         const float* __restrict__ wb,
                         float* __restrict__ Bc) {
    const int c = blockIdx.x * 128 + threadIdx.x;
    const int r = blockIdx.y;
    float v;
    if      (c < 768)  v = wq_a [r * 768  + c];
    else if (c < 1344) v = wkv_a[r * 576  + (c - 768)];
    else if (c < 2880) v = wg_w [r * 1536 + (c - 1344)];
    else if (c < 2888) v = wb   [r * 8    + (c - 2880)];
    else               v = 0.f;
    Bc[(long)r * NBIG + c] = v;
}

// ---------------- row RMS norm ----------------
__global__ void rms_kernel(const float* __restrict__ in, int inoff, int instride,
                           const float* __restrict__ w,
                           float* __restrict__ out, int n) {
    const int t = blockIdx.x;
    const float* row = in + (long)t * instride + inoff;
    float ss = 0.f;
    for (int i = threadIdx.x; i < n; i += 256) {
        float v = row[i];
        ss += v * v;
    }
    #pragma unroll
    for (int off = 16; off; off >>= 1)
        ss += __shfl_xor_sync(0xffffffffu, ss, off);
    __shared__ float red[8];
    __shared__ float scale_s;
    const int wid = threadIdx.x >> 5;
    if ((threadIdx.x & 31) == 0) red[wid] = ss;
    __syncthreads();
    if (threadIdx.x == 0) {
        float tot = 0.f;
        #pragma unroll
        for (int i = 0; i < 8; ++i) tot += red[i];
        scale_s = rsqrtf(tot / (float)n + 1e-5f);
    }
    __syncthreads();
    const float sc = scale_s;
    for (int i = threadIdx.x; i < n; i += 256)
        out[(long)t * n + i] = row[i] * sc * w[i];
}

// ---------------- prep: l2norm q (in place, *DK^-0.5), build + l2norm k ----------------
__global__ void prep_kernel(float* __restrict__ q,
                            const float* __restrict__ kv,
                            const float* __restrict__ big,
                            float* __restrict__ kf) {
    const int t = blockIdx.x >> 3;
    const int h = blockIdx.x & 7;
    const int i = threadIdx.x;  // 0..191

    const int qidx = t * (HH * DK) + h * DK + i;
    const float qv = q[qidx];
    const float kvv = (i < 128) ? kv[t * (HH * 256) + h * 256 + i]
                                : big[(long)t * NBIG + 1280 + (i - 128)];

    float q2 = qv * qv, k2 = kvv * kvv;
    #pragma unroll
    for (int off = 16; off; off >>= 1) {
        q2 += __shfl_xor_sync(0xffffffffu, q2, off);
        k2 += __shfl_xor_sync(0xffffffffu, k2, off);
    }
    __shared__ float sq[6], sk[6];
    __shared__ float scl[2];
    const int wid = threadIdx.x >> 5;
    if ((threadIdx.x & 31) == 0) { sq[wid] = q2; sk[wid] = k2; }
    __syncthreads();
    if (threadIdx.x == 0) {
        float a = 0.f, b = 0.f;
        #pragma unroll
        for (int j = 0; j < 6; ++j) { a += sq[j]; b += sk[j]; }
        scl[0] = rsqrtf(a + 1e-6f) * 0.07216878364870322f;
        scl[1] = rsqrtf(b + 1e-6f);
    }
    __syncthreads();
    q[qidx] = qv * scl[0];
    kf[qidx] = kvv * scl[1];
}

// ---------------- KDA recurrence: one warp per (h, v) column ----------------
struct RecIn {
    float2 e0, e1, e2, k0, k1, k2, q0, q1, q2;
    float vt, bt;
};

__global__ __launch_bounds__(256)
void kda_rec(const float* __restrict__ qf,
             const float* __restrict__ kf,
             const float* __restrict__ big,
             const float* __restrict__ kv,
             float* __restrict__ o) {
    const int warp = (blockIdx.x * blockDim.x + threadIdx.x) >> 5;  // 0..1023
    const int lane = threadIdx.x & 31;
    const int h = warp >> 7;
    const int v = warp & 127;

    float s0 = 0.f, s1 = 0.f, s2 = 0.f, s3 = 0.f, s4 = 0.f, s5 = 0.f;
    const int kbase = h * DK + lane * 6;

    #define RLOAD(I, t) do {                                                   \
        const int rb = (t) * (HH * DK) + kbase;                                \
        const float* ep = big + (long)(t) * NBIG + 1344 + kbase;               \
        (I).e0 = *(const float2*)(ep);     (I).e1 = *(const float2*)(ep + 2);  \
        (I).e2 = *(const float2*)(ep + 4);                                     \
        (I).k0 = *(const float2*)(kf + rb);     (I).k1 = *(const float2*)(kf + rb + 2); \
        (I).k2 = *(const float2*)(kf + rb + 4);                                \
        (I).q0 = *(const float2*)(qf + rb);     (I).q1 = *(const float2*)(qf + rb + 2); \
        (I).q2 = *(const float2*)(qf + rb + 4);                                \
        (I).vt = kv[(t) * (HH * 256) + h * 256 + 128 + v];                     \
        (I).bt = big[(long)(t) * NBIG + 2880 + h];                             \
    } while (0)

    #define RSTEP(I, t) do {                                                   \
        s0 *= (I).e0.x; s1 *= (I).e0.y; s2 *= (I).e1.x;                        \
        s3 *= (I).e1.y; s4 *= (I).e2.x; s5 *= (I).e2.y;                        \
        float kse = fmaf(s0, (I).k0.x, fmaf(s1, (I).k0.y, fmaf(s2, (I).k1.x,   \
                    fmaf(s3, (I).k1.y, fmaf(s4, (I).k2.x, s5 * (I).k2.y)))));  \
        float qse = fmaf(s0, (I).q0.x, fmaf(s1, (I).q0.y, fmaf(s2, (I).q1.x,   \
                    fmaf(s3, (I).q1.y, fmaf(s4, (I).q2.x, s5 * (I).q2.y)))));  \
        float qk  = fmaf((I).k0.x, (I).q0.x, fmaf((I).k0.y, (I).q0.y,          \
                    fmaf((I).k1.x, (I).q1.x, fmaf((I).k1.y, (I).q1.y,          \
                    fmaf((I).k2.x, (I).q2.x, (I).k2.y * (I).q2.y)))));         \
        _Pragma("unroll")                                                      \
        for (int off = 16; off; off >>= 1) {                                   \
            kse += __shfl_xor_sync(0xffffffffu, kse, off);                     \
            qse += __shfl_xor_sync(0xffffffffu, qse, off);                     \
            qk  += __shfl_xor_sync(0xffffffffu, qk,  off);                     \
        }                                                                      \
        const float u = (I).bt * ((I).vt - kse);                               \
        float ov = fmaf(qk, u, qse);                                           \
        s0 = fmaf((I).k0.x, u, s0); s1 = fmaf((I).k0.y, u, s1);                \
        s2 = fmaf((I).k1.x, u, s2); s3 = fmaf((I).k1.y, u, s3);                \
        s4 = fmaf((I).k2.x, u, s4); s5 = fmaf((I).k2.y, u, s5);                \
        if (lane == 0) {                                                       \
            if (ov != ov) ov = 0.f;                                            \
            ov = fminf(fmaxf(ov, -10000.f), 10000.f);                          \
            o[(t) * (HH * DV) + h * DV + v] = ov;                              \
        }                                                                      \
    } while (0)

    RecIn ia, ib;
    RLOAD(ia, 0);
    for (int t = 0; t < TT; t += 2) {
        RLOAD(ib, t + 1);
        RSTEP(ia, t);
        if (t + 2 < TT) RLOAD(ia, t + 2);
        RSTEP(ib, t + 1);
    }
    #undef RLOAD
    #undef RSTEP
}

// ---------------- launch ----------------
extern "C" void kernel_launch(void* const* d_in, const int* in_sizes, int n_in,
                              void* d_out, int out_size) {
    (void)in_sizes; (void)n_in; (void)out_size;
    const float* x         = (const float*)d_in[0];
    // d_in[1] = cos, d_in[2] = sin : unused by the reference
    const float* wq_a      = (const float*)d_in[3];
    const float* q_norm_w  = (const float*)d_in[4];
    const float* wq_b      = (const float*)d_in[5];
    const float* wkv_a     = (const float*)d_in[6];
    const float* kv_norm_w = (const float*)d_in[7];
    const float* wkv_b     = (const float*)d_in[8];
    const float* wg_w      = (const float*)d_in[9];
    const float* wg_b      = (const float*)d_in[10];
    const float* wb        = (const float*)d_in[11];
    const float* wo        = (const float*)d_in[12];
    float* out = (float*)d_out;

    float *bc, *big, *qn, *kvn, *q, *kv, *kf, *ov;
    cudaGetSymbolAddress((void**)&bc,  d_bc);
    cudaGetSymbolAddress((void**)&big, d_big);
    cudaGetSymbolAddress((void**)&qn,  d_qn);
    cudaGetSymbolAddress((void**)&kvn, d_kvn);
    cudaGetSymbolAddress((void**)&q,   d_q);
    cudaGetSymbolAddress((void**)&kv,  d_kv);
    cudaGetSymbolAddress((void**)&kf,  d_kf);
    cudaGetSymbolAddress((void**)&ov,  d_ov);

    // Stage 0: concat stage-1 weights
    concat_w<<<dim3(NBIG / 128, DIMX), 128>>>(wq_a, wkv_a, wg_w, wb, bc);

    // Stage 1: one wide tensor-core GEMM (+ sigmoid epilogues for g, beta)
    tgemm_kernel<1, 1><<<dim3(NBIG / BN, TT / BM), 256>>>(NBIG, DIMX, x, DIMX, bc, NBIG, wg_b, big, NBIG);

    // Stage 2: RMS norms (read from big)
    rms_kernel<<<TT, 256>>>(big, 0,   NBIG, q_norm_w,  qn,  QLR);
    rms_kernel<<<TT, 256>>>(big, 768, NBIG, kv_norm_w, kvn, KVLR);

    // Stage 3: batched up-projections (z routes problem)
    tgemm_dual_kernel<<<dim3(2048 / BN, TT / BM, 2), 256>>>(
        1536, QLR,  qn,  wq_b,  q,
        2048, KVLR, kvn, wkv_b, kv);

    // Stage 4: l2norm q/k, assemble k
    prep_kernel<<<TT * HH, 192>>>(q, kv, big, kf);

    // Stage 5: sequential KDA recurrence
    kda_rec<<<128, 256>>>(q, kf, big, kv, ov);

    // Stage 6: output projection in 3xTF32 (accuracy headroom)
    tgemm_kernel<0, 3><<<dim3(DIMX / BN, TT / BM), 256>>>(DIMX, DIMX, ov, DIMX, wo, DIMX, nullptr, out, DIMX);
}

// round 6
// speedup vs baseline: 3.9032x; 1.1023x over previous
#include <cuda_runtime.h>
#include <math.h>

// Problem constants
#define TT    1024
#define DIMX  1024
#define HH    8
#define DK    192
#define DV    128
#define QLR   768
#define KVLR  512
#define DROPE 64

// Stage-1 concatenated layout (columns of big buffer):
//   [0,768) qa | [768,1344) kva (k_pe at 1280) | [1344,2880) eg | [2880,2888) beta | pad
#define NBIG 2944

// ---------------- scratch ----------------
__device__ float d_bc  [DIMX * NBIG];
__device__ float d_big [TT * NBIG];
__device__ float d_qn  [TT * QLR];
__device__ float d_kvn [TT * KVLR];
__device__ float d_q   [TT * HH * DK];
__device__ float d_kv  [TT * HH * 256];
__device__ float d_kf  [TT * HH * DK];
__device__ float d_ov  [TT * HH * DV];

// ================= TF32 tensor-core GEMM (double-buffered, cp.async B) =================
#define BM 64
#define BN 128
#define BK 16

__device__ __forceinline__ unsigned f2tf(float f) {
    unsigned u;
    asm("cvt.rna.tf32.f32 %0, %1;" : "=r"(u) : "f"(f));
    return u;
}

__device__ __forceinline__ void mma_tf32(float* c, const unsigned* a, const unsigned* b) {
    asm volatile(
        "mma.sync.aligned.m16n8k8.row.col.f32.tf32.tf32.f32 "
        "{%0,%1,%2,%3}, {%4,%5,%6,%7}, {%8,%9}, {%0,%1,%2,%3};\n"
        : "+f"(c[0]), "+f"(c[1]), "+f"(c[2]), "+f"(c[3])
        : "r"(a[0]), "r"(a[1]), "r"(a[2]), "r"(a[3]), "r"(b[0]), "r"(b[1]));
}

__device__ __forceinline__ void cp16(float* dst, const float* src) {
    unsigned s = (unsigned)__cvta_generic_to_shared(dst);
    asm volatile("cp.async.ca.shared.global [%0], [%1], 16;\n" :: "r"(s), "l"(src));
}
#define CP_COMMIT() asm volatile("cp.async.commit_group;\n" ::: "memory")
#define CP_WAIT0()  asm volatile("cp.async.wait_group 0;\n" ::: "memory")

// EPI: 0 none, 1 = stage-1 epilogue (sigmoid for g/beta column ranges)
__device__ __forceinline__ float epi1(float v, int gc, const float* __restrict__ bias) {
    if (gc >= 1344 && gc < 2888) {
        float b = (gc < 2880) ? bias[gc - 1344] : 0.f;
        v = 1.f / (1.f + expf(-(v + b)));
    }
    return v;
}

// smem holds RAW fp32 (A transposed+swizzled, B swizzled); tf32 cvt at fragment load.
// PREC: 1 = tf32, 3 = 3xTF32 (hi/lo split in registers).
template <int EPI, int PREC>
__device__ __forceinline__ void tgemm_core(int N, int K,
                                           const float* __restrict__ A, int lda,
                                           const float* __restrict__ B, int ldb,
                                           const float* __restrict__ bias,
                                           float* __restrict__ C, int ldc,
                                           float* sA, float* sB) {
    constexpr int PL = (PREC == 3) ? 2 : 1;

    const int tid  = threadIdx.x;             // 256 threads = 8 warps
    const int crow = blockIdx.y * BM;
    const int ccol = blockIdx.x * BN;

    const int wid  = tid >> 5;
    const int lane = tid & 31;
    const int lq   = lane >> 2;
    const int lr   = lane & 3;
    const int rm   = (wid & 1) * 32;   // 2 warps in M
    const int cn   = (wid >> 1) * 32;  // 4 warps in N

    const int am  = tid >> 2;          // 0..63
    const int ak4 = (tid & 3) * 4;     // 0,4,8,12
    const int bk  = tid >> 4;          // 0..15
    const int bc8 = (tid & 15) * 8;    // 0..120
    const int swb = (((bk & 3) ^ ((bk >> 2) & 3)) << 3);

    float acc[2][4][4] = {};
    float4 aR;

    // ---- prologue: tile 0 ----
    aR = *reinterpret_cast<const float4*>(&A[(long)(crow + am) * lda + ak4]);
    cp16(&sB[bk * BN + ((bc8) ^ swb)],     &B[(long)bk * ldb + ccol + bc8]);
    cp16(&sB[bk * BN + ((bc8 + 4) ^ swb)], &B[(long)bk * ldb + ccol + bc8 + 4]);
    CP_COMMIT();
    {
        const float av[4] = {aR.x, aR.y, aR.z, aR.w};
        #pragma unroll
        for (int i = 0; i < 4; ++i) {
            const int k  = ak4 + i;
            const int sw = (((k & 3) ^ ((k >> 2) & 3)) << 3);
            sA[k * BM + (am ^ sw)] = av[i];
        }
    }
    if (K > BK)
        aR = *reinterpret_cast<const float4*>(&A[(long)(crow + am) * lda + BK + ak4]);
    CP_WAIT0();
    __syncthreads();

    int buf = 0;
    for (int k0 = 0; k0 < K; k0 += BK, buf ^= 1) {
        float* cA = sA + buf * (BK * BM);
        float* cB = sB + buf * (BK * BN);
        const int nxt = buf ^ 1;

        // ---- issue next tile into the other buffer ----
        if (k0 + BK < K) {
            float* nB = sB + nxt * (BK * BN);
            cp16(&nB[bk * BN + ((bc8) ^ swb)],     &B[(long)(k0 + BK + bk) * ldb + ccol + bc8]);
            cp16(&nB[bk * BN + ((bc8 + 4) ^ swb)], &B[(long)(k0 + BK + bk) * ldb + ccol + bc8 + 4]);
            CP_COMMIT();
            float* nA = sA + nxt * (BK * BM);
            const float av[4] = {aR.x, aR.y, aR.z, aR.w};
            #pragma unroll
            for (int i = 0; i < 4; ++i) {
                const int k  = ak4 + i;
                const int sw = (((k & 3) ^ ((k >> 2) & 3)) << 3);
                nA[k * BM + (am ^ sw)] = av[i];
            }
            if (k0 + 2 * BK < K)
                aR = *reinterpret_cast<const float4*>(&A[(long)(crow + am) * lda + k0 + 2 * BK + ak4]);
        }

        // ---- compute on current buffer ----
        #pragma unroll
        for (int k8 = 0; k8 < BK; k8 += 8) {
            const int f0 = ((lr ^ (k8 >> 2)) & 3) << 3;
            const int f1 = f0 ^ 8;
            unsigned af[PL][2][4], bf[PL][4][2];
            #pragma unroll
            for (int mt = 0; mt < 2; ++mt) {
                const int r = rm + mt * 16 + lq;
                float r0 = cA[(k8 + lr) * BM + (r ^ f0)];
                float r1 = cA[(k8 + lr) * BM + ((r + 8) ^ f0)];
                float r2 = cA[(k8 + lr + 4) * BM + (r ^ f1)];
                float r3 = cA[(k8 + lr + 4) * BM + ((r + 8) ^ f1)];
                af[0][mt][0] = f2tf(r0); af[0][mt][1] = f2tf(r1);
                af[0][mt][2] = f2tf(r2); af[0][mt][3] = f2tf(r3);
                if (PREC == 3) {
                    af[1][mt][0] = f2tf(r0 - __uint_as_float(af[0][mt][0]));
                    af[1][mt][1] = f2tf(r1 - __uint_as_float(af[0][mt][1]));
                    af[1][mt][2] = f2tf(r2 - __uint_as_float(af[0][mt][2]));
                    af[1][mt][3] = f2tf(r3 - __uint_as_float(af[0][mt][3]));
                }
            }
            #pragma unroll
            for (int nt = 0; nt < 4; ++nt) {
                const int c = cn + nt * 8 + lq;
                float r0 = cB[(k8 + lr) * BN + (c ^ f0)];
                float r1 = cB[(k8 + lr + 4) * BN + (c ^ f1)];
                bf[0][nt][0] = f2tf(r0); bf[0][nt][1] = f2tf(r1);
                if (PREC == 3) {
                    bf[1][nt][0] = f2tf(r0 - __uint_as_float(bf[0][nt][0]));
                    bf[1][nt][1] = f2tf(r1 - __uint_as_float(bf[0][nt][1]));
                }
            }
            #pragma unroll
            for (int mt = 0; mt < 2; ++mt)
                #pragma unroll
                for (int nt = 0; nt < 4; ++nt) {
                    mma_tf32(acc[mt][nt], af[0][mt], bf[0][nt]);
                    if (PREC == 3) {
                        mma_tf32(acc[mt][nt], af[0][mt], bf[1][nt]);
                        mma_tf32(acc[mt][nt], af[1][mt], bf[0][nt]);
                    }
                }
        }
        CP_WAIT0();
        __syncthreads();
    }

    #pragma unroll
    for (int mt = 0; mt < 2; ++mt) {
        const int row = crow + rm + mt * 16 + lq;
        #pragma unroll
        for (int nt = 0; nt < 4; ++nt) {
            const int col = ccol + cn + nt * 8 + lr * 2;
            float v0 = acc[mt][nt][0], v1 = acc[mt][nt][1];
            float v2 = acc[mt][nt][2], v3 = acc[mt][nt][3];
            if (EPI == 1) {
                v0 = epi1(v0, col, bias);     v1 = epi1(v1, col + 1, bias);
                v2 = epi1(v2, col, bias);     v3 = epi1(v3, col + 1, bias);
            }
            *reinterpret_cast<float2*>(&C[(long)row * ldc + col])       = make_float2(v0, v1);
            *reinterpret_cast<float2*>(&C[(long)(row + 8) * ldc + col]) = make_float2(v2, v3);
        }
    }
}

template <int EPI, int PREC>
__global__ __launch_bounds__(256, 2)
void tgemm_kernel(int N, int K, const float* __restrict__ A, int lda,
                  const float* __restrict__ B, int ldb,
                  const float* __restrict__ bias, float* __restrict__ C, int ldc) {
    __shared__ float sA[2 * BK * BM];
    __shared__ float sB[2 * BK * BN];
    tgemm_core<EPI, PREC>(N, K, A, lda, B, ldb, bias, C, ldc, sA, sB);
}

__global__ __launch_bounds__(256, 2)
void tgemm_dual_kernel(int N0, int K0, const float* __restrict__ A0,
                       const float* __restrict__ B0, float* __restrict__ C0,
                       int N1, int K1, const float* __restrict__ A1,
                       const float* __restrict__ B1, float* __restrict__ C1) {
    __shared__ float sA[2 * BK * BM];
    __shared__ float sB[2 * BK * BN];
    if (blockIdx.z == 0) {
        if ((int)blockIdx.x * BN >= N0) return;
        tgemm_core<0, 1>(N0, K0, A0, K0, B0, N0, nullptr, C0, N0, sA, sB);
    } else {
        tgemm_core<0, 1>(N1, K1, A1, K1, B1, N1, nullptr, C1, N1, sA, sB);
    }
}

// ---------------- stage-1 weight concat ----------------
__global__ void concat_w(const float* __restrict__ wq_a,
                         const float* __restrict__ wkv_a,
                         const float* __restrict__ wg_w,
                         const float* __restrict__ wb,
                         float* __restrict__ Bc) {
    const int c = blockIdx.x * 128 + threadIdx.x;
    const int r = blockIdx.y;
    float v;
    if      (c < 768)  v = wq_a [r * 768  + c];
    else if (c < 1344) v = wkv_a[r * 576  + (c - 768)];
    else if (c < 2880) v = wg_w [r * 1536 + (c - 1344)];
    else if (c < 2888) v = wb   [r * 8    + (c - 2880)];
    else               v = 0.f;
    Bc[(long)r * NBIG + c] = v;
}

// ---------------- row RMS norm ----------------
__global__ void rms_kernel(const float* __restrict__ in, int inoff, int instride,
                           const float* __restrict__ w,
                           float* __restrict__ out, int n) {
    const int t = blockIdx.x;
    const float* row = in + (long)t * instride + inoff;
    float ss = 0.f;
    for (int i = threadIdx.x; i < n; i += 256) {
        float v = row[i];
        ss += v * v;
    }
    #pragma unroll
    for (int off = 16; off; off >>= 1)
        ss += __shfl_xor_sync(0xffffffffu, ss, off);
    __shared__ float red[8];
    __shared__ float scale_s;
    const int wid = threadIdx.x >> 5;
    if ((threadIdx.x & 31) == 0) red[wid] = ss;
    __syncthreads();
    if (threadIdx.x == 0) {
        float tot = 0.f;
        #pragma unroll
        for (int i = 0; i < 8; ++i) tot += red[i];
        scale_s = rsqrtf(tot / (float)n + 1e-5f);
    }
    __syncthreads();
    const float sc = scale_s;
    for (int i = threadIdx.x; i < n; i += 256)
        out[(long)t * n + i] = row[i] * sc * w[i];
}

// ---------------- prep: l2norm q (in place, *DK^-0.5), build + l2norm k ----------------
__global__ void prep_kernel(float* __restrict__ q,
                            const float* __restrict__ kv,
                            const float* __restrict__ big,
                            float* __restrict__ kf) {
    const int t = blockIdx.x >> 3;
    const int h = blockIdx.x & 7;
    const int i = threadIdx.x;  // 0..191

    const int qidx = t * (HH * DK) + h * DK + i;
    const float qv = q[qidx];
    const float kvv = (i < 128) ? kv[t * (HH * 256) + h * 256 + i]
                                : big[(long)t * NBIG + 1280 + (i - 128)];

    float q2 = qv * qv, k2 = kvv * kvv;
    #pragma unroll
    for (int off = 16; off; off >>= 1) {
        q2 += __shfl_xor_sync(0xffffffffu, q2, off);
        k2 += __shfl_xor_sync(0xffffffffu, k2, off);
    }
    __shared__ float sq[6], sk[6];
    __shared__ float scl[2];
    const int wid = threadIdx.x >> 5;
    if ((threadIdx.x & 31) == 0) { sq[wid] = q2; sk[wid] = k2; }
    __syncthreads();
    if (threadIdx.x == 0) {
        float a = 0.f, b = 0.f;
        #pragma unroll
        for (int j = 0; j < 6; ++j) { a += sq[j]; b += sk[j]; }
        scl[0] = rsqrtf(a + 1e-6f) * 0.07216878364870322f;
        scl[1] = rsqrtf(b + 1e-6f);
    }
    __syncthreads();
    q[qidx] = qv * scl[0];
    kf[qidx] = kvv * scl[1];
}

// ---------------- KDA recurrence: one warp per (h, v) column ----------------
struct RecIn {
    float2 e0, e1, e2, k0, k1, k2, q0, q1, q2;
    float vt, bt;
};

__global__ __launch_bounds__(256)
void kda_rec(const float* __restrict__ qf,
             const float* __restrict__ kf,
             const float* __restrict__ big,
             const float* __restrict__ kv,
             float* __restrict__ o) {
    const int warp = (blockIdx.x * blockDim.x + threadIdx.x) >> 5;  // 0..1023
    const int lane = threadIdx.x & 31;
    const int h = warp >> 7;
    const int v = warp & 127;

    float s0 = 0.f, s1 = 0.f, s2 = 0.f, s3 = 0.f, s4 = 0.f, s5 = 0.f;
    const int kbase = h * DK + lane * 6;

    #define RLOAD(I, t) do {                                                   \
        const int rb = (t) * (HH * DK) + kbase;                                \
        const float* ep = big + (long)(t) * NBIG + 1344 + kbase;               \
        (I).e0 = *(const float2*)(ep);     (I).e1 = *(const float2*)(ep + 2);  \
        (I).e2 = *(const float2*)(ep + 4);                                     \
        (I).k0 = *(const float2*)(kf + rb);     (I).k1 = *(const float2*)(kf + rb + 2); \
        (I).k2 = *(const float2*)(kf + rb + 4);                                \
        (I).q0 = *(const float2*)(qf + rb);     (I).q1 = *(const float2*)(qf + rb + 2); \
        (I).q2 = *(const float2*)(qf + rb + 4);                                \
        (I).vt = kv[(t) * (HH * 256) + h * 256 + 128 + v];                     \
        (I).bt = big[(long)(t) * NBIG + 2880 + h];                             \
    } while (0)

    #define RSTEP(I, t) do {                                                   \
        s0 *= (I).e0.x; s1 *= (I).e0.y; s2 *= (I).e1.x;                        \
        s3 *= (I).e1.y; s4 *= (I).e2.x; s5 *= (I).e2.y;                        \
        float kse = fmaf(s0, (I).k0.x, fmaf(s1, (I).k0.y, fmaf(s2, (I).k1.x,   \
                    fmaf(s3, (I).k1.y, fmaf(s4, (I).k2.x, s5 * (I).k2.y)))));  \
        float qse = fmaf(s0, (I).q0.x, fmaf(s1, (I).q0.y, fmaf(s2, (I).q1.x,   \
                    fmaf(s3, (I).q1.y, fmaf(s4, (I).q2.x, s5 * (I).q2.y)))));  \
        float qk  = fmaf((I).k0.x, (I).q0.x, fmaf((I).k0.y, (I).q0.y,          \
                    fmaf((I).k1.x, (I).q1.x, fmaf((I).k1.y, (I).q1.y,          \
                    fmaf((I).k2.x, (I).q2.x, (I).k2.y * (I).q2.y)))));         \
        _Pragma("unroll")                                                      \
        for (int off = 16; off; off >>= 1) {                                   \
            kse += __shfl_xor_sync(0xffffffffu, kse, off);                     \
            qse += __shfl_xor_sync(0xffffffffu, qse, off);                     \
            qk  += __shfl_xor_sync(0xffffffffu, qk,  off);                     \
        }                                                                      \
        const float u = (I).bt * ((I).vt - kse);                               \
        float ov = fmaf(qk, u, qse);                                           \
        s0 = fmaf((I).k0.x, u, s0); s1 = fmaf((I).k0.y, u, s1);                \
        s2 = fmaf((I).k1.x, u, s2); s3 = fmaf((I).k1.y, u, s3);                \
        s4 = fmaf((I).k2.x, u, s4); s5 = fmaf((I).k2.y, u, s5);                \
        if (lane == 0) {                                                       \
            if (ov != ov) ov = 0.f;                                            \
            ov = fminf(fmaxf(ov, -10000.f), 10000.f);                          \
            o[(t) * (HH * DV) + h * DV + v] = ov;                              \
        }                                                                      \
    } while (0)

    RecIn ia, ib;
    RLOAD(ia, 0);
    for (int t = 0; t < TT; t += 2) {
        RLOAD(ib, t + 1);
        RSTEP(ia, t);
        if (t + 2 < TT) RLOAD(ia, t + 2);
        RSTEP(ib, t + 1);
    }
    #undef RLOAD
    #undef RSTEP
}

// ---------------- launch ----------------
extern "C" void kernel_launch(void* const* d_in, const int* in_sizes, int n_in,
                              void* d_out, int out_size) {
    (void)in_sizes; (void)n_in; (void)out_size;
    const float* x         = (const float*)d_in[0];
    const float* wq_a      = (const float*)d_in[3];
    const float* q_norm_w  = (const float*)d_in[4];
    const float* wq_b      = (const float*)d_in[5];
    const float* wkv_a     = (const float*)d_in[6];
    const float* kv_norm_w = (const float*)d_in[7];
    const float* wkv_b     = (const float*)d_in[8];
    const float* wg_w      = (const float*)d_in[9];
    const float* wg_b      = (const float*)d_in[10];
    const float* wb        = (const float*)d_in[11];
    const float* wo        = (const float*)d_in[12];
    float* out = (float*)d_out;

    float *bc, *big, *qn, *kvn, *q, *kv, *kf, *ov;
    cudaGetSymbolAddress((void**)&bc,  d_bc);
    cudaGetSymbolAddress((void**)&big, d_big);
    cudaGetSymbolAddress((void**)&qn,  d_qn);
    cudaGetSymbolAddress((void**)&kvn, d_kvn);
    cudaGetSymbolAddress((void**)&q,   d_q);
    cudaGetSymbolAddress((void**)&kv,  d_kv);
    cudaGetSymbolAddress((void**)&kf,  d_kf);
    cudaGetSymbolAddress((void**)&ov,  d_ov);

    concat_w<<<dim3(NBIG / 128, DIMX), 128>>>(wq_a, wkv_a, wg_w, wb, bc);

    tgemm_kernel<1, 1><<<dim3(NBIG / BN, TT / BM), 256>>>(NBIG, DIMX, x, DIMX, bc, NBIG, wg_b, big, NBIG);

    rms_kernel<<<TT, 256>>>(big, 0,   NBIG, q_norm_w,  qn,  QLR);
    rms_kernel<<<TT, 256>>>(big, 768, NBIG, kv_norm_w, kvn, KVLR);

    tgemm_dual_kernel<<<dim3(2048 / BN, TT / BM, 2), 256>>>(
        1536, QLR,  qn,  wq_b,  q,
        2048, KVLR, kvn, wkv_b, kv);

    prep_kernel<<<TT * HH, 192>>>(q, kv, big, kf);

    kda_rec<<<128, 256>>>(q, kf, big, kv, ov);

    tgemm_kernel<0, 3><<<dim3(DIMX / BN, TT / BM), 256>>>(DIMX, DIMX, ov, DIMX, wo, DIMX, nullptr, out, DIMX);
}